// round 6
// baseline (speedup 1.0000x reference)
#include <cuda_runtime.h>
#include <cuda_bf16.h>
#include <math.h>

// ---------------------------------------------------------------------------
// Decoder_11811160064753 : full decoder forward
//   inputs (metadata order):
//   0 x[8,256,32,32] 1 skip1[8,128,64,64] 2 skip2[8,256,32,32]
//   3..10 rb{0,1}_{w1,b1,w2,b2}
//   11 conv1_w 12 conv1_b 13 conv3_w 14 conv3_b 15 conv5_w 16 conv5_b
//   17 conv6_w 18 conv6_b
//   19 dcn2_off_w 20 dcn2_off_b 21 dcn2_w 22 dcn2_b
//   23 dcn1_off_w 24 dcn1_off_b 25 dcn1_w 26 dcn1_b
//   output: image [8,3,128,128] (393216 floats) then offset_sum scalar (1 float)
// ---------------------------------------------------------------------------

#define BATCH 8

// ------------------------- scratch arena (device .bss) ---------------------
// sizes in floats
static const size_t SZ_A    = 8ull*256*32*32;   // 2,097,152
static const size_t SZ_B    = SZ_A;
static const size_t SZ_C    = SZ_A;
static const size_t SZ_DC2  = 8ull*512*32*32;   // 4,194,304
static const size_t SZ_OUT3 = SZ_DC2;
static const size_t SZ_OM2  = 8ull*27*32*32;    // 221,184
static const size_t SZ_COL2 = 8ull*256*9*32*32; // 18,874,368
static const size_t SZ_T64  = 8ull*128*64*64;   // 4,194,304
static const size_t SZ_DC1  = 8ull*256*64*64;   // 8,388,608
static const size_t SZ_OUT5 = SZ_DC1;
static const size_t SZ_OM1  = 8ull*27*64*64;    // 884,736
static const size_t SZ_COL1 = 8ull*128*9*64*64; // 37,748,736
static const size_t SZ_T128 = 8ull*64*128*128;  // 8,388,608
static const size_t SZ_STAT = 4096;
static const size_t SZ_PART = 64;

static const size_t OFF_A    = 0;
static const size_t OFF_B    = OFF_A    + SZ_A;
static const size_t OFF_C    = OFF_B    + SZ_B;
static const size_t OFF_DC2  = OFF_C    + SZ_C;
static const size_t OFF_OUT3 = OFF_DC2  + SZ_DC2;
static const size_t OFF_OM2  = OFF_OUT3 + SZ_OUT3;
static const size_t OFF_COL2 = OFF_OM2  + SZ_OM2;
static const size_t OFF_T64  = OFF_COL2 + SZ_COL2;
static const size_t OFF_DC1  = OFF_T64  + SZ_T64;
static const size_t OFF_OUT5 = OFF_DC1  + SZ_DC1;
static const size_t OFF_OM1  = OFF_OUT5 + SZ_OUT5;
static const size_t OFF_COL1 = OFF_OM1  + SZ_OM1;
static const size_t OFF_T128 = OFF_COL1 + SZ_COL1;
static const size_t OFF_MEAN = OFF_T128 + SZ_T128;
static const size_t OFF_RSTD = OFF_MEAN + SZ_STAT;
static const size_t OFF_PA   = OFF_RSTD + SZ_STAT;   // partials for om2
static const size_t OFF_PB   = OFF_PA   + SZ_PART;   // partials for om1
static const size_t ARENA_SZ = OFF_PB   + SZ_PART;

__device__ float g_arena[ARENA_SZ];

// ------------------------------ generic conv -------------------------------
// Direct conv, output tile 32 wide x (8*NPIX) tall per block, 256 threads.
// Each thread: NPIX pixels (rows ty + 8*j), NCO output channels.
// Input & weights staged via shared memory in CCH-channel chunks.
// REFLECT: reflect padding (else zero). UPS: input is 2x-nearest-upsampled
// on the fly (stored dims H/2 x W/2, coords computed in output space).
template<int K, int CCH, int NCO, int NPIX, bool REFLECT, bool UPS>
__global__ void __launch_bounds__(256)
conv_kernel(const float* __restrict__ in, const float* __restrict__ wgt,
            const float* __restrict__ bias, float* __restrict__ out,
            int Cin, int Cout, int H, int W, int pad,
            int outCtot, int outCbase, int act)
{
    constexpr int TW_ = 32;
    constexpr int TH_ = 8 * NPIX;
    constexpr int SW  = TW_ + K - 1;
    constexpr int SH  = TH_ + K - 1;
    constexpr int KK  = K * K;

    __shared__ float s_in[CCH * SH * SW];
    __shared__ float s_w [CCH * NCO * KK];

    const int tid    = threadIdx.x;
    const int tilesX = W >> 5;
    const int tX     = blockIdx.x % tilesX;
    const int tY     = blockIdx.x / tilesX;
    const int coBase = blockIdx.y * NCO;
    const int b      = blockIdx.z;
    const int tx     = tid & 31;
    const int ty     = tid >> 5;

    const int Hin = UPS ? (H >> 1) : H;
    const int Win = UPS ? (W >> 1) : W;
    const float* inB = in + (size_t)b * Cin * Hin * Win;

    float acc[NCO][NPIX];
#pragma unroll
    for (int i = 0; i < NCO; i++)
#pragma unroll
        for (int j = 0; j < NPIX; j++) acc[i][j] = 0.f;

    const int y0g = tY * TH_ - pad;
    const int x0g = tX * TW_ - pad;

    for (int c0 = 0; c0 < Cin; c0 += CCH) {
        // stage input tile
        for (int i = tid; i < CCH * SH * SW; i += 256) {
            int cc = i / (SH * SW);
            int r  = i - cc * (SH * SW);
            int sy = r / SW;
            int sx = r - sy * SW;
            int gy = y0g + sy, gx = x0g + sx;
            float v = 0.f;
            int ci = c0 + cc;
            if (ci < Cin) {
                bool ok = true;
                int my = gy, mx = gx;
                if (REFLECT) {
                    my = gy < 0 ? -gy : (gy >= H ? 2 * H - 2 - gy : gy);
                    mx = gx < 0 ? -gx : (gx >= W ? 2 * W - 2 - gx : gx);
                } else {
                    ok = (gy >= 0) && (gy < H) && (gx >= 0) && (gx < W);
                }
                if (ok) {
                    int yy = UPS ? (my >> 1) : my;
                    int xx = UPS ? (mx >> 1) : mx;
                    v = inB[(size_t)ci * (Hin * Win) + yy * Win + xx];
                }
            }
            s_in[i] = v;
        }
        // stage weights: layout s_w[(cc*NCO + co)*KK + t]
        for (int i = tid; i < CCH * NCO * KK; i += 256) {
            int cc  = i / (NCO * KK);
            int r   = i - cc * (NCO * KK);
            int co  = r / KK;
            int t   = r - co * KK;
            int ci  = c0 + cc;
            int gco = coBase + co;
            s_w[i] = (ci < Cin && gco < Cout)
                   ? wgt[((size_t)gco * Cin + ci) * KK + t] : 0.f;
        }
        __syncthreads();

#pragma unroll
        for (int cc = 0; cc < CCH; cc++) {
            const float* si = &s_in[cc * SH * SW];
            const float* sw = &s_w [cc * NCO * KK];
#pragma unroll 1
            for (int ky = 0; ky < K; ky++) {
                const float* row0 = si + (ty + ky) * SW + tx;
#pragma unroll
                for (int kx = 0; kx < K; kx++) {
                    float v[NPIX];
#pragma unroll
                    for (int j = 0; j < NPIX; j++)
                        v[j] = row0[j * 8 * SW + kx];
                    const int t = ky * K + kx;
#pragma unroll
                    for (int co = 0; co < NCO; co++) {
                        float wv = sw[co * KK + t];
#pragma unroll
                        for (int j = 0; j < NPIX; j++)
                            acc[co][j] = fmaf(v[j], wv, acc[co][j]);
                    }
                }
            }
        }
        __syncthreads();
    }

    const int oxa = tX * TW_ + tx;
#pragma unroll
    for (int co = 0; co < NCO; co++) {
        int gco = coBase + co;
        if (gco >= Cout) break;
        float bb = bias[gco];
        size_t base = ((size_t)(b * outCtot + outCbase + gco)) * H * W;
#pragma unroll
        for (int j = 0; j < NPIX; j++) {
            float r = acc[co][j] + bb;
            if (act) r = tanhf(r);
            out[base + (size_t)(tY * TH_ + ty + 8 * j) * W + oxa] = r;
        }
    }
}

// ------------------------- instance-norm statistics ------------------------
__global__ void stats_kernel(const float* __restrict__ x,
                             float* __restrict__ mean, float* __restrict__ rstd,
                             int HW)
{
    int bc = blockIdx.x;
    const float* p = x + (size_t)bc * HW;
    float s = 0.f, s2 = 0.f;
    for (int i = threadIdx.x; i < HW; i += 256) {
        float v = p[i]; s += v; s2 += v * v;
    }
#pragma unroll
    for (int o = 16; o; o >>= 1) {
        s  += __shfl_down_sync(0xffffffffu, s,  o);
        s2 += __shfl_down_sync(0xffffffffu, s2, o);
    }
    __shared__ float ss[8], ss2[8];
    int w = threadIdx.x >> 5, l = threadIdx.x & 31;
    if (l == 0) { ss[w] = s; ss2[w] = s2; }
    __syncthreads();
    if (threadIdx.x == 0) {
        float S = 0.f, S2 = 0.f;
        for (int i = 0; i < 8; i++) { S += ss[i]; S2 += ss2[i]; }
        float m = S / HW;
        float v = S2 / HW - m * m;
        if (v < 0.f) v = 0.f;
        mean[bc] = m;
        rstd[bc] = rsqrtf(v + 1e-5f);
    }
}

// ------------- normalize (+relu | +residual) with dual destination ---------
__global__ void norm_apply(const float* __restrict__ x, const float* __restrict__ res,
                           float* __restrict__ o1, float* __restrict__ o2,
                           const float* __restrict__ mean, const float* __restrict__ rstd,
                           int C, int HW, int c1tot, int c1base,
                           int c2tot, int c2base, int relu, int N)
{
    int i = blockIdx.x * 256 + threadIdx.x;
    if (i >= N) return;
    int hw = i % HW;
    int bc = i / HW;
    int c  = bc % C;
    int b  = bc / C;
    float v = (x[i] - mean[bc]) * rstd[bc];
    if (relu) v = fmaxf(v, 0.f);
    if (res)  v += res[i];
    o1[((size_t)(b * c1tot + c1base + c)) * HW + hw] = v;
    if (o2) o2[((size_t)(b * c2tot + c2base + c)) * HW + hw] = v;
}

// ------------------- channel-slice copy (build concat buffers) -------------
__global__ void copy_ch(const float* __restrict__ src, float* __restrict__ dst,
                        int C, int HW, int ctot, int cbase, int N)
{
    int i = blockIdx.x * 256 + threadIdx.x;
    if (i >= N) return;
    int hw = i % HW;
    int bc = i / HW;
    int c  = bc % C;
    int b  = bc / C;
    dst[((size_t)(b * ctot + cbase + c)) * HW + hw] = src[i];
}

// --------------- deformable-conv column builder (bilinear+mask) ------------
// om layout [B,27,HW]: ch 0..17 interleaved (dy,dx) per tap, ch 18..26 mask.
// col layout [B, C, 9, HW] == [B, C*9, HW] channel index ci*9+k.
__global__ void dcn_col(const float* __restrict__ img, const float* __restrict__ om,
                        float* __restrict__ col, int C, int H, int W)
{
    int p = blockIdx.x * 256 + threadIdx.x;
    int k = blockIdx.y;
    int b = blockIdx.z;
    int HW = H * W;
    if (p >= HW) return;
    int y = p / W, x = p % W;

    const float* omB = om + (size_t)b * 27 * HW;
    float dy = omB[(2 * k    ) * HW + p];
    float dx = omB[(2 * k + 1) * HW + p];
    float mv = 1.f / (1.f + expf(-omB[(18 + k) * HW + p]));

    float py = (float)(y + k / 3 - 1) + dy;
    float px = (float)(x + k % 3 - 1) + dx;
    float fy = floorf(py), fx = floorf(px);
    int y0 = (int)fy, x0 = (int)fx;
    float wy1 = py - fy, wx1 = px - fx;
    float wy0 = 1.f - wy1, wx0 = 1.f - wx1;

    bool vy0 = (y0 >= 0)     && (y0 < H);
    bool vy1 = (y0 + 1 >= 0) && (y0 + 1 < H);
    bool vx0 = (x0 >= 0)     && (x0 < W);
    bool vx1 = (x0 + 1 >= 0) && (x0 + 1 < W);

    float w00 = (vy0 && vx0) ? wy0 * wx0 * mv : 0.f;
    float w01 = (vy0 && vx1) ? wy0 * wx1 * mv : 0.f;
    float w10 = (vy1 && vx0) ? wy1 * wx0 * mv : 0.f;
    float w11 = (vy1 && vx1) ? wy1 * wx1 * mv : 0.f;

    int cy0 = min(max(y0, 0), H - 1);
    int cy1 = min(max(y0 + 1, 0), H - 1);
    int cx0 = min(max(x0, 0), W - 1);
    int cx1 = min(max(x0 + 1, 0), W - 1);
    int i00 = cy0 * W + cx0, i01 = cy0 * W + cx1;
    int i10 = cy1 * W + cx0, i11 = cy1 * W + cx1;

    const float* ib = img + (size_t)b * C * HW;
    float* cb = col + ((size_t)b * C * 9 + k) * HW + p;
    for (int ci = 0; ci < C; ci++) {
        const float* ic = ib + (size_t)ci * HW;
        float v = w00 * ic[i00] + w01 * ic[i01] + w10 * ic[i10] + w11 * ic[i11];
        cb[(size_t)ci * 9 * HW] = v;
    }
}

// ------------------------ |offset| mean reductions --------------------------
__global__ void absmean_partial(const float* __restrict__ om,
                                float* __restrict__ part, int HW)
{
    long N = 144L * HW;  // 8 batches * 18 channels
    float s = 0.f;
    long stride = 64L * 256;
    for (long i = (long)blockIdx.x * 256 + threadIdx.x; i < N; i += stride) {
        int hw = (int)(i % HW);
        int t  = (int)(i / HW);
        int c = t % 18, b = t / 18;
        s += fabsf(om[((size_t)b * 27 + c) * HW + hw]);
    }
#pragma unroll
    for (int o = 16; o; o >>= 1) s += __shfl_down_sync(0xffffffffu, s, o);
    __shared__ float sh[8];
    if ((threadIdx.x & 31) == 0) sh[threadIdx.x >> 5] = s;
    __syncthreads();
    if (threadIdx.x == 0) {
        float t2 = 0.f;
        for (int i = 0; i < 8; i++) t2 += sh[i];
        part[blockIdx.x] = t2;
    }
}

__global__ void finalize_offset(const float* __restrict__ pA, const float* __restrict__ pB,
                                float* __restrict__ dst, float invA, float invB)
{
    float sA = 0.f, sB = 0.f;
    for (int i = 0; i < 64; i++) { sA += pA[i]; sB += pB[i]; }
    dst[0] = 0.5f * (sA * invA + sB * invB);
}

// -------------------------------- host side --------------------------------
static inline dim3 cgrid(int H, int W, int Cout, int NCO, int TH)
{
    return dim3((unsigned)((W / 32) * (H / TH)),
                (unsigned)((Cout + NCO - 1) / NCO), BATCH);
}

extern "C" void kernel_launch(void* const* d_in, const int* in_sizes, int n_in,
                              void* d_out, int out_size)
{
    (void)in_sizes; (void)n_in; (void)out_size;
    const float* x        = (const float*)d_in[0];
    const float* skip1    = (const float*)d_in[1];
    const float* skip2    = (const float*)d_in[2];
    const float* rb_w1[2] = {(const float*)d_in[3], (const float*)d_in[7]};
    const float* rb_b1[2] = {(const float*)d_in[4], (const float*)d_in[8]};
    const float* rb_w2[2] = {(const float*)d_in[5], (const float*)d_in[9]};
    const float* rb_b2[2] = {(const float*)d_in[6], (const float*)d_in[10]};
    const float* conv1_w = (const float*)d_in[11]; const float* conv1_b = (const float*)d_in[12];
    const float* conv3_w = (const float*)d_in[13]; const float* conv3_b = (const float*)d_in[14];
    const float* conv5_w = (const float*)d_in[15]; const float* conv5_b = (const float*)d_in[16];
    const float* conv6_w = (const float*)d_in[17]; const float* conv6_b = (const float*)d_in[18];
    const float* dcn2_ow = (const float*)d_in[19]; const float* dcn2_ob = (const float*)d_in[20];
    const float* dcn2_w  = (const float*)d_in[21]; const float* dcn2_b  = (const float*)d_in[22];
    const float* dcn1_ow = (const float*)d_in[23]; const float* dcn1_ob = (const float*)d_in[24];
    const float* dcn1_w  = (const float*)d_in[25]; const float* dcn1_b  = (const float*)d_in[26];
    float* out = (float*)d_out;

    float* arena = nullptr;
    cudaGetSymbolAddress((void**)&arena, g_arena);
    float* A    = arena + OFF_A;
    float* Bf   = arena + OFF_B;
    float* Cf   = arena + OFF_C;
    float* dc2  = arena + OFF_DC2;
    float* out3 = arena + OFF_OUT3;
    float* om2  = arena + OFF_OM2;
    float* col2 = arena + OFF_COL2;
    float* t64  = arena + OFF_T64;
    float* dc1  = arena + OFF_DC1;
    float* out5 = arena + OFF_OUT5;
    float* om1  = arena + OFF_OM1;
    float* col1 = arena + OFF_COL1;
    float* t128 = arena + OFF_T128;
    float* gm   = arena + OFF_MEAN;
    float* gr   = arena + OFF_RSTD;
    float* pA   = arena + OFF_PA;
    float* pB   = arena + OFF_PB;

    auto c3r = conv_kernel<3, 4, 32, 2, true,  false>;
    auto c3z = conv_kernel<3, 4, 32, 2, false, false>;
    auto c5r = conv_kernel<5, 2, 32, 2, true,  false>;
    auto c5u = conv_kernel<5, 2, 32, 2, true,  true >;
    auto c7r = conv_kernel<7, 2, 32, 2, true,  false>;
    auto c1k = conv_kernel<1, 16, 64, 1, false, false>;

    const int N32_256 = 8 * 256 * 1024;  // 2,097,152
    const int N64_128 = 8 * 128 * 4096;  // 4,194,304
    const int N128_64 = 8 * 64 * 16384;  // 8,388,608

    // ---- ResBlock 0 ----
    c3r<<<cgrid(32, 32, 256, 32, 16), 256>>>(x,  rb_w1[0], rb_b1[0], A, 256, 256, 32, 32, 1, 256, 0, 0);
    stats_kernel<<<8 * 256, 256>>>(A, gm, gr, 1024);
    norm_apply<<<(N32_256 + 255) / 256, 256>>>(A, nullptr, Bf, nullptr, gm, gr, 256, 1024, 256, 0, 0, 0, 1, N32_256);
    c3r<<<cgrid(32, 32, 256, 32, 16), 256>>>(Bf, rb_w2[0], rb_b2[0], A, 256, 256, 32, 32, 1, 256, 0, 0);
    stats_kernel<<<8 * 256, 256>>>(A, gm, gr, 1024);
    norm_apply<<<(N32_256 + 255) / 256, 256>>>(A, x, Cf, nullptr, gm, gr, 256, 1024, 256, 0, 0, 0, 0, N32_256);

    // ---- ResBlock 1 ----
    c3r<<<cgrid(32, 32, 256, 32, 16), 256>>>(Cf, rb_w1[1], rb_b1[1], A, 256, 256, 32, 32, 1, 256, 0, 0);
    stats_kernel<<<8 * 256, 256>>>(A, gm, gr, 1024);
    norm_apply<<<(N32_256 + 255) / 256, 256>>>(A, nullptr, Bf, nullptr, gm, gr, 256, 1024, 256, 0, 0, 0, 1, N32_256);
    c3r<<<cgrid(32, 32, 256, 32, 16), 256>>>(Bf, rb_w2[1], rb_b2[1], A, 256, 256, 32, 32, 1, 256, 0, 0);
    stats_kernel<<<8 * 256, 256>>>(A, gm, gr, 1024);
    norm_apply<<<(N32_256 + 255) / 256, 256>>>(A, Cf, Bf, nullptr, gm, gr, 256, 1024, 256, 0, 0, 0, 0, N32_256);
    // out1 in Bf

    // ---- Conv2dBlock 5x5 256->256 ----
    c5r<<<cgrid(32, 32, 256, 32, 16), 256>>>(Bf, conv1_w, conv1_b, A, 256, 256, 32, 32, 2, 256, 0, 0);
    stats_kernel<<<8 * 256, 256>>>(A, gm, gr, 1024);
    // out2 -> dc2[ch 0:256] and out3[ch 256:512]
    norm_apply<<<(N32_256 + 255) / 256, 256>>>(A, nullptr, dc2, out3, gm, gr, 256, 1024, 512, 0, 512, 256, 1, N32_256);
    copy_ch<<<(N32_256 + 255) / 256, 256>>>(skip2, dc2, 256, 1024, 512, 256, N32_256);

    // ---- DCN2 ----
    c3z<<<cgrid(32, 32, 27, 32, 16), 256>>>(dc2, dcn2_ow, dcn2_ob, om2, 512, 27, 32, 32, 1, 27, 0, 0);
    dcn_col<<<dim3(4, 9, BATCH), 256>>>(skip2, om2, col2, 256, 32, 32);
    c1k<<<cgrid(32, 32, 256, 64, 8), 256>>>(col2, dcn2_w, dcn2_b, out3, 2304, 256, 32, 32, 0, 512, 0, 0);
    absmean_partial<<<64, 256>>>(om2, pA, 1024);

    // ---- upsample(x2) fused + Conv2dBlock 5x5 512->128 ----
    c5u<<<cgrid(64, 64, 128, 32, 16), 256>>>(out3, conv3_w, conv3_b, t64, 512, 128, 64, 64, 2, 128, 0, 0);
    stats_kernel<<<8 * 128, 256>>>(t64, gm, gr, 4096);
    // out4 -> dc1[ch 0:128] and out5[ch 128:256]
    norm_apply<<<(N64_128 + 255) / 256, 256>>>(t64, nullptr, dc1, out5, gm, gr, 128, 4096, 256, 0, 256, 128, 1, N64_128);
    copy_ch<<<(N64_128 + 255) / 256, 256>>>(skip1, dc1, 128, 4096, 256, 128, N64_128);

    // ---- DCN1 ----
    c3z<<<cgrid(64, 64, 27, 32, 16), 256>>>(dc1, dcn1_ow, dcn1_ob, om1, 256, 27, 64, 64, 1, 27, 0, 0);
    dcn_col<<<dim3(16, 9, BATCH), 256>>>(skip1, om1, col1, 128, 64, 64);
    c1k<<<cgrid(64, 64, 128, 64, 8), 256>>>(col1, dcn1_w, dcn1_b, out5, 1152, 128, 64, 64, 0, 256, 0, 0);
    absmean_partial<<<64, 256>>>(om1, pB, 4096);

    // ---- upsample(x2) fused + Conv2dBlock 5x5 256->64 ----
    c5u<<<cgrid(128, 128, 64, 32, 16), 256>>>(out5, conv5_w, conv5_b, t128, 256, 64, 128, 128, 2, 64, 0, 0);
    stats_kernel<<<8 * 64, 256>>>(t128, gm, gr, 16384);
    norm_apply<<<(N128_64 + 255) / 256, 256>>>(t128, nullptr, t128, nullptr, gm, gr, 64, 16384, 64, 0, 0, 0, 1, N128_64);

    // ---- final 7x7 64->3 + tanh, straight to d_out ----
    c7r<<<cgrid(128, 128, 3, 32, 16), 256>>>(t128, conv6_w, conv6_b, out, 64, 3, 128, 128, 3, 3, 0, 1);

    // ---- offset_sum scalar at end of d_out ----
    finalize_offset<<<1, 1>>>(pA, pB, out + 8 * 3 * 128 * 128,
                              1.f / 147456.f, 1.f / 589824.f);
}

// round 7
// speedup vs baseline: 1.4258x; 1.4258x over previous
#include <cuda_runtime.h>
#include <cuda_bf16.h>
#include <math.h>

// ---------------------------------------------------------------------------
// Decoder_11811160064753 : full decoder forward
// ---------------------------------------------------------------------------

#define BATCH 8

// ------------------------- scratch arena (device .bss) ---------------------
static const size_t SZ_A    = 8ull*256*32*32;   // 2,097,152
static const size_t SZ_B    = SZ_A;
static const size_t SZ_C    = SZ_A;
static const size_t SZ_DC2  = 8ull*512*32*32;   // 4,194,304
static const size_t SZ_OUT3 = SZ_DC2;
static const size_t SZ_OM2  = 4ull*8*27*32*32;  // 4 slices
static const size_t SZ_COL2 = 8ull*256*9*32*32; // 18,874,368
static const size_t SZ_T64  = 8ull*128*64*64;   // 4,194,304
static const size_t SZ_DC1  = 8ull*256*64*64;   // 8,388,608
static const size_t SZ_OUT5 = SZ_DC1;
static const size_t SZ_OM1  = 2ull*8*27*64*64;  // 2 slices
static const size_t SZ_COL1 = 8ull*128*9*64*64; // 37,748,736
static const size_t SZ_T128 = 8ull*64*128*128;  // 8,388,608
static const size_t SZ_STAT = 4096;
static const size_t SZ_PART = 64;

static const size_t OFF_A    = 0;
static const size_t OFF_B    = OFF_A    + SZ_A;
static const size_t OFF_C    = OFF_B    + SZ_B;
static const size_t OFF_DC2  = OFF_C    + SZ_C;
static const size_t OFF_OUT3 = OFF_DC2  + SZ_DC2;
static const size_t OFF_OM2  = OFF_OUT3 + SZ_OUT3;
static const size_t OFF_COL2 = OFF_OM2  + SZ_OM2;
static const size_t OFF_T64  = OFF_COL2 + SZ_COL2;
static const size_t OFF_DC1  = OFF_T64  + SZ_T64;
static const size_t OFF_OUT5 = OFF_DC1  + SZ_DC1;
static const size_t OFF_OM1  = OFF_OUT5 + SZ_OUT5;
static const size_t OFF_COL1 = OFF_OM1  + SZ_OM1;
static const size_t OFF_T128 = OFF_COL1 + SZ_COL1;
static const size_t OFF_MEAN = OFF_T128 + SZ_T128;
static const size_t OFF_RSTD = OFF_MEAN + SZ_STAT;
static const size_t OFF_PA   = OFF_RSTD + SZ_STAT;
static const size_t OFF_PB   = OFF_PA   + SZ_PART;
static const size_t ARENA_SZ = OFF_PB   + SZ_PART;

__device__ float g_arena[ARENA_SZ];

// ------------------------------ generic conv -------------------------------
// Output tile 32 wide x 16 tall (NPIX=2 rows/thread), 256 threads.
// NCO output channels per block; weights staged in smem as [cc][tap][co] so
// the inner loop reads them as float4 (4 co per LDS128).
// Cin-split support: nSlices partial reductions, slice s handles channels
// [s*cinPer, (s+1)*cinPer) and writes to out + s*sliceStride (bias on s==0).
template<int K, int CCH, int NCO, int NPIX, bool REFLECT, bool UPS>
__global__ void __launch_bounds__(256, 3)
conv_kernel(const float* __restrict__ in, const float* __restrict__ wgt,
            const float* __restrict__ bias, float* __restrict__ out,
            int Cin, int Cout, int H, int W, int pad,
            int outCtot, int outCbase, int act,
            int cinPer, int nSlices, size_t sliceStride)
{
    constexpr int TW_ = 32;
    constexpr int TH_ = 8 * NPIX;
    constexpr int SW  = TW_ + K - 1;
    constexpr int SH  = TH_ + K - 1;
    constexpr int KK  = K * K;

    __shared__ __align__(16) float s_in[CCH * SH * SW];
    __shared__ __align__(16) float s_w [CCH * KK * NCO];

    const int tid    = threadIdx.x;
    const int tilesX = W >> 5;
    const int tX     = blockIdx.x % tilesX;
    const int tY     = blockIdx.x / tilesX;
    const int coBase = blockIdx.y * NCO;
    const int zb     = blockIdx.z;
    const int sl     = zb % nSlices;
    const int b      = zb / nSlices;
    const int tx     = tid & 31;
    const int ty     = tid >> 5;

    const int Hin = UPS ? (H >> 1) : H;
    const int Win = UPS ? (W >> 1) : W;
    const float* inB = in + (size_t)b * Cin * Hin * Win;

    float acc[NCO][NPIX];
#pragma unroll
    for (int i = 0; i < NCO; i++)
#pragma unroll
        for (int j = 0; j < NPIX; j++) acc[i][j] = 0.f;

    const int y0g = tY * TH_ - pad;
    const int x0g = tX * TW_ - pad;

    const int cBeg = sl * cinPer;
    const int cEnd = min(Cin, cBeg + cinPer);

    for (int c0 = cBeg; c0 < cEnd; c0 += CCH) {
        // stage input tile
        for (int i = tid; i < CCH * SH * SW; i += 256) {
            int cc = i / (SH * SW);
            int r  = i - cc * (SH * SW);
            int sy = r / SW;
            int sx = r - sy * SW;
            int gy = y0g + sy, gx = x0g + sx;
            float v = 0.f;
            int ci = c0 + cc;
            if (ci < cEnd) {
                bool ok = true;
                int my = gy, mx = gx;
                if (REFLECT) {
                    my = gy < 0 ? -gy : (gy >= H ? 2 * H - 2 - gy : gy);
                    mx = gx < 0 ? -gx : (gx >= W ? 2 * W - 2 - gx : gx);
                } else {
                    ok = (gy >= 0) && (gy < H) && (gx >= 0) && (gx < W);
                }
                if (ok) {
                    int yy = UPS ? (my >> 1) : my;
                    int xx = UPS ? (mx >> 1) : mx;
                    v = inB[(size_t)ci * (Hin * Win) + yy * Win + xx];
                }
            }
            s_in[i] = v;
        }
        // stage weights: s_w[(cc*KK + t)*NCO + co]
        for (int i = tid; i < CCH * KK * NCO; i += 256) {
            int co  = i % NCO;
            int t   = (i / NCO) % KK;
            int cc  = i / (NCO * KK);
            int ci  = c0 + cc;
            int gco = coBase + co;
            s_w[i] = (ci < cEnd && gco < Cout)
                   ? wgt[((size_t)gco * Cin + ci) * KK + t] : 0.f;
        }
        __syncthreads();

#pragma unroll
        for (int cc = 0; cc < CCH; cc++) {
            const float* si = &s_in[cc * SH * SW];
#pragma unroll 1
            for (int ky = 0; ky < K; ky++) {
                const float*  row0 = si + (ty + ky) * SW + tx;
                const float4* swr  = (const float4*)&s_w[(cc * KK + ky * K) * NCO];
#pragma unroll
                for (int kx = 0; kx < K; kx++) {
                    float v[NPIX];
#pragma unroll
                    for (int j = 0; j < NPIX; j++)
                        v[j] = row0[j * 8 * SW + kx];
                    const float4* swt = swr + kx * (NCO / 4);
#pragma unroll
                    for (int q = 0; q < NCO / 4; q++) {
                        float4 w4 = swt[q];
#pragma unroll
                        for (int j = 0; j < NPIX; j++) {
                            acc[4*q+0][j] = fmaf(v[j], w4.x, acc[4*q+0][j]);
                            acc[4*q+1][j] = fmaf(v[j], w4.y, acc[4*q+1][j]);
                            acc[4*q+2][j] = fmaf(v[j], w4.z, acc[4*q+2][j]);
                            acc[4*q+3][j] = fmaf(v[j], w4.w, acc[4*q+3][j]);
                        }
                    }
                }
            }
        }
        __syncthreads();
    }

    float* outS = out + (size_t)sl * sliceStride;
    const int oxa = tX * TW_ + tx;
#pragma unroll
    for (int co = 0; co < NCO; co++) {
        int gco = coBase + co;
        if (gco >= Cout) break;
        float bb = (sl == 0) ? bias[gco] : 0.f;
        size_t base = ((size_t)(b * outCtot + outCbase + gco)) * H * W;
#pragma unroll
        for (int j = 0; j < NPIX; j++) {
            float r = acc[co][j] + bb;
            if (act) r = tanhf(r);
            outS[base + (size_t)(tY * TH_ + ty + 8 * j) * W + oxa] = r;
        }
    }
}

// ------------------------- instance-norm statistics ------------------------
__global__ void stats_kernel(const float* __restrict__ x,
                             float* __restrict__ mean, float* __restrict__ rstd,
                             int HW)
{
    int bc = blockIdx.x;
    const float* p = x + (size_t)bc * HW;
    float s = 0.f, s2 = 0.f;
    for (int i = threadIdx.x; i < HW; i += 256) {
        float v = p[i]; s += v; s2 += v * v;
    }
#pragma unroll
    for (int o = 16; o; o >>= 1) {
        s  += __shfl_down_sync(0xffffffffu, s,  o);
        s2 += __shfl_down_sync(0xffffffffu, s2, o);
    }
    __shared__ float ss[8], ss2[8];
    int w = threadIdx.x >> 5, l = threadIdx.x & 31;
    if (l == 0) { ss[w] = s; ss2[w] = s2; }
    __syncthreads();
    if (threadIdx.x == 0) {
        float S = 0.f, S2 = 0.f;
        for (int i = 0; i < 8; i++) { S += ss[i]; S2 += ss2[i]; }
        float m = S / HW;
        float v = S2 / HW - m * m;
        if (v < 0.f) v = 0.f;
        mean[bc] = m;
        rstd[bc] = rsqrtf(v + 1e-5f);
    }
}

// ------------- normalize (+relu | +residual) with dual destination ---------
__global__ void norm_apply(const float* __restrict__ x, const float* __restrict__ res,
                           float* __restrict__ o1, float* __restrict__ o2,
                           const float* __restrict__ mean, const float* __restrict__ rstd,
                           int C, int HW, int c1tot, int c1base,
                           int c2tot, int c2base, int relu, int N)
{
    int i = blockIdx.x * 256 + threadIdx.x;
    if (i >= N) return;
    int hw = i % HW;
    int bc = i / HW;
    int c  = bc % C;
    int b  = bc / C;
    float v = (x[i] - mean[bc]) * rstd[bc];
    if (relu) v = fmaxf(v, 0.f);
    if (res)  v += res[i];
    o1[((size_t)(b * c1tot + c1base + c)) * HW + hw] = v;
    if (o2) o2[((size_t)(b * c2tot + c2base + c)) * HW + hw] = v;
}

// ------------------- channel-slice copy (build concat buffers) -------------
__global__ void copy_ch(const float* __restrict__ src, float* __restrict__ dst,
                        int C, int HW, int ctot, int cbase, int N)
{
    int i = blockIdx.x * 256 + threadIdx.x;
    if (i >= N) return;
    int hw = i % HW;
    int bc = i / HW;
    int c  = bc % C;
    int b  = bc / C;
    dst[((size_t)(b * ctot + cbase + c)) * HW + hw] = src[i];
}

// --------------- deformable-conv column builder (bilinear+mask) ------------
// om is stored as nSlices partial buffers (stride floats apart) to be summed.
__global__ void dcn_col(const float* __restrict__ img, const float* __restrict__ om,
                        float* __restrict__ col, int C, int H, int W,
                        int nSlices, size_t stride)
{
    int p = blockIdx.x * 256 + threadIdx.x;
    int k = blockIdx.y;
    int b = blockIdx.z;
    int HW = H * W;
    if (p >= HW) return;
    int y = p / W, x = p % W;

    size_t base = (size_t)b * 27 * HW;
    float dy = 0.f, dx = 0.f, mr = 0.f;
    for (int s = 0; s < nSlices; s++) {
        const float* omS = om + s * stride + base;
        dy += omS[(2 * k    ) * HW + p];
        dx += omS[(2 * k + 1) * HW + p];
        mr += omS[(18 + k) * HW + p];
    }
    float mv = 1.f / (1.f + expf(-mr));

    float py = (float)(y + k / 3 - 1) + dy;
    float px = (float)(x + k % 3 - 1) + dx;
    float fy = floorf(py), fx = floorf(px);
    int y0 = (int)fy, x0 = (int)fx;
    float wy1 = py - fy, wx1 = px - fx;
    float wy0 = 1.f - wy1, wx0 = 1.f - wx1;

    bool vy0 = (y0 >= 0)     && (y0 < H);
    bool vy1 = (y0 + 1 >= 0) && (y0 + 1 < H);
    bool vx0 = (x0 >= 0)     && (x0 < W);
    bool vx1 = (x0 + 1 >= 0) && (x0 + 1 < W);

    float w00 = (vy0 && vx0) ? wy0 * wx0 * mv : 0.f;
    float w01 = (vy0 && vx1) ? wy0 * wx1 * mv : 0.f;
    float w10 = (vy1 && vx0) ? wy1 * wx0 * mv : 0.f;
    float w11 = (vy1 && vx1) ? wy1 * wx1 * mv : 0.f;

    int cy0 = min(max(y0, 0), H - 1);
    int cy1 = min(max(y0 + 1, 0), H - 1);
    int cx0 = min(max(x0, 0), W - 1);
    int cx1 = min(max(x0 + 1, 0), W - 1);
    int i00 = cy0 * W + cx0, i01 = cy0 * W + cx1;
    int i10 = cy1 * W + cx0, i11 = cy1 * W + cx1;

    const float* ib = img + (size_t)b * C * HW;
    float* cb = col + ((size_t)b * C * 9 + k) * HW + p;
    for (int ci = 0; ci < C; ci++) {
        const float* ic = ib + (size_t)ci * HW;
        float v = w00 * ic[i00] + w01 * ic[i01] + w10 * ic[i10] + w11 * ic[i11];
        cb[(size_t)ci * 9 * HW] = v;
    }
}

// ------------------------ |offset| mean reductions --------------------------
__global__ void absmean_partial(const float* __restrict__ om,
                                float* __restrict__ part, int HW,
                                int nSlices, size_t stride)
{
    long N = 144L * HW;  // 8 batches * 18 channels
    float s = 0.f;
    long gs = 64L * 256;
    for (long i = (long)blockIdx.x * 256 + threadIdx.x; i < N; i += gs) {
        int hw = (int)(i % HW);
        int t  = (int)(i / HW);
        int c = t % 18, b = t / 18;
        size_t idx = ((size_t)b * 27 + c) * HW + hw;
        float v = 0.f;
        for (int sl = 0; sl < nSlices; sl++) v += om[sl * stride + idx];
        s += fabsf(v);
    }
#pragma unroll
    for (int o = 16; o; o >>= 1) s += __shfl_down_sync(0xffffffffu, s, o);
    __shared__ float sh[8];
    if ((threadIdx.x & 31) == 0) sh[threadIdx.x >> 5] = s;
    __syncthreads();
    if (threadIdx.x == 0) {
        float t2 = 0.f;
        for (int i = 0; i < 8; i++) t2 += sh[i];
        part[blockIdx.x] = t2;
    }
}

__global__ void finalize_offset(const float* __restrict__ pA, const float* __restrict__ pB,
                                float* __restrict__ dst, float invA, float invB)
{
    float sA = 0.f, sB = 0.f;
    for (int i = 0; i < 64; i++) { sA += pA[i]; sB += pB[i]; }
    dst[0] = 0.5f * (sA * invA + sB * invB);
}

// -------------------------------- host side --------------------------------
static inline dim3 cgrid(int H, int W, int Cout, int zMul = 1)
{
    return dim3((unsigned)((W / 32) * (H / 16)),
                (unsigned)((Cout + 15) / 16), BATCH * zMul);
}

extern "C" void kernel_launch(void* const* d_in, const int* in_sizes, int n_in,
                              void* d_out, int out_size)
{
    (void)in_sizes; (void)n_in; (void)out_size;
    const float* x        = (const float*)d_in[0];
    const float* skip1    = (const float*)d_in[1];
    const float* skip2    = (const float*)d_in[2];
    const float* rb_w1[2] = {(const float*)d_in[3], (const float*)d_in[7]};
    const float* rb_b1[2] = {(const float*)d_in[4], (const float*)d_in[8]};
    const float* rb_w2[2] = {(const float*)d_in[5], (const float*)d_in[9]};
    const float* rb_b2[2] = {(const float*)d_in[6], (const float*)d_in[10]};
    const float* conv1_w = (const float*)d_in[11]; const float* conv1_b = (const float*)d_in[12];
    const float* conv3_w = (const float*)d_in[13]; const float* conv3_b = (const float*)d_in[14];
    const float* conv5_w = (const float*)d_in[15]; const float* conv5_b = (const float*)d_in[16];
    const float* conv6_w = (const float*)d_in[17]; const float* conv6_b = (const float*)d_in[18];
    const float* dcn2_ow = (const float*)d_in[19]; const float* dcn2_ob = (const float*)d_in[20];
    const float* dcn2_w  = (const float*)d_in[21]; const float* dcn2_b  = (const float*)d_in[22];
    const float* dcn1_ow = (const float*)d_in[23]; const float* dcn1_ob = (const float*)d_in[24];
    const float* dcn1_w  = (const float*)d_in[25]; const float* dcn1_b  = (const float*)d_in[26];
    float* out = (float*)d_out;

    float* arena = nullptr;
    cudaGetSymbolAddress((void**)&arena, g_arena);
    float* A    = arena + OFF_A;
    float* Bf   = arena + OFF_B;
    float* Cf   = arena + OFF_C;
    float* dc2  = arena + OFF_DC2;
    float* out3 = arena + OFF_OUT3;
    float* om2  = arena + OFF_OM2;
    float* col2 = arena + OFF_COL2;
    float* t64  = arena + OFF_T64;
    float* dc1  = arena + OFF_DC1;
    float* out5 = arena + OFF_OUT5;
    float* om1  = arena + OFF_OM1;
    float* col1 = arena + OFF_COL1;
    float* t128 = arena + OFF_T128;
    float* gm   = arena + OFF_MEAN;
    float* gr   = arena + OFF_RSTD;
    float* pA   = arena + OFF_PA;
    float* pB   = arena + OFF_PB;

    auto c3r = conv_kernel<3, 4, 16, 2, true,  false>;
    auto c3z = conv_kernel<3, 4, 16, 2, false, false>;
    auto c5r = conv_kernel<5, 2, 16, 2, true,  false>;
    auto c5u = conv_kernel<5, 2, 16, 2, true,  true >;
    auto c7r = conv_kernel<7, 2, 16, 2, true,  false>;
    auto c1k = conv_kernel<1, 16, 16, 2, false, false>;

    const int N32_256 = 8 * 256 * 1024;
    const int N64_128 = 8 * 128 * 4096;
    const int N128_64 = 8 * 64 * 16384;

    const size_t OM2_SL = (size_t)8 * 27 * 1024;
    const size_t OM1_SL = (size_t)8 * 27 * 4096;

    // ---- ResBlock 0 ----
    c3r<<<cgrid(32, 32, 256), 256>>>(x,  rb_w1[0], rb_b1[0], A, 256, 256, 32, 32, 1, 256, 0, 0, 256, 1, 0);
    stats_kernel<<<8 * 256, 256>>>(A, gm, gr, 1024);
    norm_apply<<<(N32_256 + 255) / 256, 256>>>(A, nullptr, Bf, nullptr, gm, gr, 256, 1024, 256, 0, 0, 0, 1, N32_256);
    c3r<<<cgrid(32, 32, 256), 256>>>(Bf, rb_w2[0], rb_b2[0], A, 256, 256, 32, 32, 1, 256, 0, 0, 256, 1, 0);
    stats_kernel<<<8 * 256, 256>>>(A, gm, gr, 1024);
    norm_apply<<<(N32_256 + 255) / 256, 256>>>(A, x, Cf, nullptr, gm, gr, 256, 1024, 256, 0, 0, 0, 0, N32_256);

    // ---- ResBlock 1 ----
    c3r<<<cgrid(32, 32, 256), 256>>>(Cf, rb_w1[1], rb_b1[1], A, 256, 256, 32, 32, 1, 256, 0, 0, 256, 1, 0);
    stats_kernel<<<8 * 256, 256>>>(A, gm, gr, 1024);
    norm_apply<<<(N32_256 + 255) / 256, 256>>>(A, nullptr, Bf, nullptr, gm, gr, 256, 1024, 256, 0, 0, 0, 1, N32_256);
    c3r<<<cgrid(32, 32, 256), 256>>>(Bf, rb_w2[1], rb_b2[1], A, 256, 256, 32, 32, 1, 256, 0, 0, 256, 1, 0);
    stats_kernel<<<8 * 256, 256>>>(A, gm, gr, 1024);
    norm_apply<<<(N32_256 + 255) / 256, 256>>>(A, Cf, Bf, nullptr, gm, gr, 256, 1024, 256, 0, 0, 0, 0, N32_256);
    // out1 in Bf

    // ---- Conv2dBlock 5x5 256->256 ----
    c5r<<<cgrid(32, 32, 256), 256>>>(Bf, conv1_w, conv1_b, A, 256, 256, 32, 32, 2, 256, 0, 0, 256, 1, 0);
    stats_kernel<<<8 * 256, 256>>>(A, gm, gr, 1024);
    norm_apply<<<(N32_256 + 255) / 256, 256>>>(A, nullptr, dc2, out3, gm, gr, 256, 1024, 512, 0, 512, 256, 1, N32_256);
    copy_ch<<<(N32_256 + 255) / 256, 256>>>(skip2, dc2, 256, 1024, 512, 256, N32_256);

    // ---- DCN2 (offset conv split 4-way over Cin=512) ----
    c3z<<<cgrid(32, 32, 27, 4), 256>>>(dc2, dcn2_ow, dcn2_ob, om2, 512, 27, 32, 32, 1, 27, 0, 0, 128, 4, OM2_SL);
    dcn_col<<<dim3(4, 9, BATCH), 256>>>(skip2, om2, col2, 256, 32, 32, 4, OM2_SL);
    c1k<<<cgrid(32, 32, 256), 256>>>(col2, dcn2_w, dcn2_b, out3, 2304, 256, 32, 32, 0, 512, 0, 0, 2304, 1, 0);
    absmean_partial<<<64, 256>>>(om2, pA, 1024, 4, OM2_SL);

    // ---- upsample(x2) fused + Conv2dBlock 5x5 512->128 ----
    c5u<<<cgrid(64, 64, 128), 256>>>(out3, conv3_w, conv3_b, t64, 512, 128, 64, 64, 2, 128, 0, 0, 512, 1, 0);
    stats_kernel<<<8 * 128, 256>>>(t64, gm, gr, 4096);
    norm_apply<<<(N64_128 + 255) / 256, 256>>>(t64, nullptr, dc1, out5, gm, gr, 128, 4096, 256, 0, 256, 128, 1, N64_128);
    copy_ch<<<(N64_128 + 255) / 256, 256>>>(skip1, dc1, 128, 4096, 256, 128, N64_128);

    // ---- DCN1 (offset conv split 2-way over Cin=256) ----
    c3z<<<cgrid(64, 64, 27, 2), 256>>>(dc1, dcn1_ow, dcn1_ob, om1, 256, 27, 64, 64, 1, 27, 0, 0, 128, 2, OM1_SL);
    dcn_col<<<dim3(16, 9, BATCH), 256>>>(skip1, om1, col1, 128, 64, 64, 2, OM1_SL);
    c1k<<<cgrid(64, 64, 128), 256>>>(col1, dcn1_w, dcn1_b, out5, 1152, 128, 64, 64, 0, 256, 0, 0, 1152, 1, 0);
    absmean_partial<<<64, 256>>>(om1, pB, 4096, 2, OM1_SL);

    // ---- upsample(x2) fused + Conv2dBlock 5x5 256->64 ----
    c5u<<<cgrid(128, 128, 64), 256>>>(out5, conv5_w, conv5_b, t128, 256, 64, 128, 128, 2, 64, 0, 0, 256, 1, 0);
    stats_kernel<<<8 * 64, 256>>>(t128, gm, gr, 16384);
    norm_apply<<<(N128_64 + 255) / 256, 256>>>(t128, nullptr, t128, nullptr, gm, gr, 64, 16384, 64, 0, 0, 0, 1, N128_64);

    // ---- final 7x7 64->3 + tanh, straight to d_out ----
    c7r<<<cgrid(128, 128, 3), 256>>>(t128, conv6_w, conv6_b, out, 64, 3, 128, 128, 3, 3, 0, 1, 64, 1, 0);

    // ---- offset_sum scalar at end of d_out ----
    finalize_offset<<<1, 1>>>(pA, pB, out + 8 * 3 * 128 * 128,
                              1.f / 147456.f, 1.f / 589824.f);
}

// round 8
// speedup vs baseline: 1.4308x; 1.0035x over previous
#include <cuda_runtime.h>
#include <cuda_bf16.h>
#include <math.h>

// ---------------------------------------------------------------------------
// Decoder_11811160064753 : full decoder forward
// ---------------------------------------------------------------------------

#define BATCH 8

// ------------------------- scratch arena (device .bss) ---------------------
static const size_t SZ_A    = 8ull*256*32*32;   // 2,097,152
static const size_t SZ_B    = SZ_A;
static const size_t SZ_C    = SZ_A;
static const size_t SZ_DC2  = 8ull*512*32*32;   // 4,194,304
static const size_t SZ_OUT3 = SZ_DC2;
static const size_t SZ_OM2  = 4ull*8*27*32*32;  // 4 slices
static const size_t SZ_COL2 = 8ull*256*9*32*32; // 18,874,368
static const size_t SZ_T64  = 8ull*128*64*64;   // 4,194,304
static const size_t SZ_DC1  = 8ull*256*64*64;   // 8,388,608
static const size_t SZ_OUT5 = SZ_DC1;
static const size_t SZ_OM1  = 2ull*8*27*64*64;  // 2 slices
static const size_t SZ_COL1 = 8ull*128*9*64*64; // 37,748,736
static const size_t SZ_T128 = 8ull*64*128*128;  // 8,388,608
static const size_t SZ_STAT = 4096;
static const size_t SZ_PART = 64;

static const size_t OFF_A    = 0;
static const size_t OFF_B    = OFF_A    + SZ_A;
static const size_t OFF_C    = OFF_B    + SZ_B;
static const size_t OFF_DC2  = OFF_C    + SZ_C;
static const size_t OFF_OUT3 = OFF_DC2  + SZ_DC2;
static const size_t OFF_OM2  = OFF_OUT3 + SZ_OUT3;
static const size_t OFF_COL2 = OFF_OM2  + SZ_OM2;
static const size_t OFF_T64  = OFF_COL2 + SZ_COL2;
static const size_t OFF_DC1  = OFF_T64  + SZ_T64;
static const size_t OFF_OUT5 = OFF_DC1  + SZ_DC1;
static const size_t OFF_OM1  = OFF_OUT5 + SZ_OUT5;
static const size_t OFF_COL1 = OFF_OM1  + SZ_OM1;
static const size_t OFF_T128 = OFF_COL1 + SZ_COL1;
static const size_t OFF_MEAN = OFF_T128 + SZ_T128;
static const size_t OFF_RSTD = OFF_MEAN + SZ_STAT;
static const size_t OFF_PA   = OFF_RSTD + SZ_STAT;
static const size_t OFF_PB   = OFF_PA   + SZ_PART;
static const size_t ARENA_SZ = OFF_PB   + SZ_PART;

__device__ float g_arena[ARENA_SZ];

// ------------------------------ generic conv -------------------------------
// Output tile 32 wide x 16 tall (NPIX=2 rows/thread), 256 threads.
// NCO output channels per block; weights staged in smem as [cc][tap][co] so
// the inner loop reads them as float4 (4 co per LDS128).
// Cin-split support: nSlices partial reductions, slice s handles channels
// [s*cinPer, (s+1)*cinPer) and writes to out + s*sliceStride (bias on s==0).
template<int K, int CCH, int NCO, int NPIX, bool REFLECT, bool UPS>
__global__ void __launch_bounds__(256, 3)
conv_kernel(const float* __restrict__ in, const float* __restrict__ wgt,
            const float* __restrict__ bias, float* __restrict__ out,
            int Cin, int Cout, int H, int W, int pad,
            int outCtot, int outCbase, int act,
            int cinPer, int nSlices, size_t sliceStride)
{
    constexpr int TW_ = 32;
    constexpr int TH_ = 8 * NPIX;
    constexpr int SW  = TW_ + K - 1;
    constexpr int SH  = TH_ + K - 1;
    constexpr int KK  = K * K;

    __shared__ __align__(16) float s_in[CCH * SH * SW];
    __shared__ __align__(16) float s_w [CCH * KK * NCO];

    const int tid    = threadIdx.x;
    const int tilesX = W >> 5;
    const int tX     = blockIdx.x % tilesX;
    const int tY     = blockIdx.x / tilesX;
    const int coBase = blockIdx.y * NCO;
    const int zb     = blockIdx.z;
    const int sl     = zb % nSlices;
    const int b      = zb / nSlices;
    const int tx     = tid & 31;
    const int ty     = tid >> 5;

    const int Hin = UPS ? (H >> 1) : H;
    const int Win = UPS ? (W >> 1) : W;
    const float* inB = in + (size_t)b * Cin * Hin * Win;

    float acc[NCO][NPIX];
#pragma unroll
    for (int i = 0; i < NCO; i++)
#pragma unroll
        for (int j = 0; j < NPIX; j++) acc[i][j] = 0.f;

    const int y0g = tY * TH_ - pad;
    const int x0g = tX * TW_ - pad;

    const int cBeg = sl * cinPer;
    const int cEnd = min(Cin, cBeg + cinPer);

    for (int c0 = cBeg; c0 < cEnd; c0 += CCH) {
        // stage input tile
        for (int i = tid; i < CCH * SH * SW; i += 256) {
            int cc = i / (SH * SW);
            int r  = i - cc * (SH * SW);
            int sy = r / SW;
            int sx = r - sy * SW;
            int gy = y0g + sy, gx = x0g + sx;
            float v = 0.f;
            int ci = c0 + cc;
            if (ci < cEnd) {
                bool ok = true;
                int my = gy, mx = gx;
                if (REFLECT) {
                    my = gy < 0 ? -gy : (gy >= H ? 2 * H - 2 - gy : gy);
                    mx = gx < 0 ? -gx : (gx >= W ? 2 * W - 2 - gx : gx);
                } else {
                    ok = (gy >= 0) && (gy < H) && (gx >= 0) && (gx < W);
                }
                if (ok) {
                    int yy = UPS ? (my >> 1) : my;
                    int xx = UPS ? (mx >> 1) : mx;
                    v = inB[(size_t)ci * (Hin * Win) + yy * Win + xx];
                }
            }
            s_in[i] = v;
        }
        // stage weights: s_w[(cc*KK + t)*NCO + co]
        for (int i = tid; i < CCH * KK * NCO; i += 256) {
            int co  = i % NCO;
            int t   = (i / NCO) % KK;
            int cc  = i / (NCO * KK);
            int ci  = c0 + cc;
            int gco = coBase + co;
            s_w[i] = (ci < cEnd && gco < Cout)
                   ? wgt[((size_t)gco * Cin + ci) * KK + t] : 0.f;
        }
        __syncthreads();

#pragma unroll
        for (int cc = 0; cc < CCH; cc++) {
            const float* si = &s_in[cc * SH * SW];
#pragma unroll 1
            for (int ky = 0; ky < K; ky++) {
                const float*  row0 = si + (ty + ky) * SW + tx;
                const float4* swr  = (const float4*)&s_w[(cc * KK + ky * K) * NCO];
#pragma unroll
                for (int kx = 0; kx < K; kx++) {
                    float v[NPIX];
#pragma unroll
                    for (int j = 0; j < NPIX; j++)
                        v[j] = row0[j * 8 * SW + kx];
                    const float4* swt = swr + kx * (NCO / 4);
#pragma unroll
                    for (int q = 0; q < NCO / 4; q++) {
                        float4 w4 = swt[q];
#pragma unroll
                        for (int j = 0; j < NPIX; j++) {
                            acc[4*q+0][j] = fmaf(v[j], w4.x, acc[4*q+0][j]);
                            acc[4*q+1][j] = fmaf(v[j], w4.y, acc[4*q+1][j]);
                            acc[4*q+2][j] = fmaf(v[j], w4.z, acc[4*q+2][j]);
                            acc[4*q+3][j] = fmaf(v[j], w4.w, acc[4*q+3][j]);
                        }
                    }
                }
            }
        }
        __syncthreads();
    }

    float* outS = out + (size_t)sl * sliceStride;
    const int oxa = tX * TW_ + tx;
#pragma unroll
    for (int co = 0; co < NCO; co++) {
        int gco = coBase + co;
        if (gco >= Cout) break;
        float bb = (sl == 0) ? bias[gco] : 0.f;
        size_t base = ((size_t)(b * outCtot + outCbase + gco)) * H * W;
#pragma unroll
        for (int j = 0; j < NPIX; j++) {
            float r = acc[co][j] + bb;
            if (act) r = tanhf(r);
            outS[base + (size_t)(tY * TH_ + ty + 8 * j) * W + oxa] = r;
        }
    }
}

// ------------------------- instance-norm statistics ------------------------
__global__ void stats_kernel(const float* __restrict__ x,
                             float* __restrict__ mean, float* __restrict__ rstd,
                             int HW)
{
    int bc = blockIdx.x;
    const float* p = x + (size_t)bc * HW;
    float s = 0.f, s2 = 0.f;
    for (int i = threadIdx.x; i < HW; i += 256) {
        float v = p[i]; s += v; s2 += v * v;
    }
#pragma unroll
    for (int o = 16; o; o >>= 1) {
        s  += __shfl_down_sync(0xffffffffu, s,  o);
        s2 += __shfl_down_sync(0xffffffffu, s2, o);
    }
    __shared__ float ss[8], ss2[8];
    int w = threadIdx.x >> 5, l = threadIdx.x & 31;
    if (l == 0) { ss[w] = s; ss2[w] = s2; }
    __syncthreads();
    if (threadIdx.x == 0) {
        float S = 0.f, S2 = 0.f;
        for (int i = 0; i < 8; i++) { S += ss[i]; S2 += ss2[i]; }
        float m = S / HW;
        float v = S2 / HW - m * m;
        if (v < 0.f) v = 0.f;
        mean[bc] = m;
        rstd[bc] = rsqrtf(v + 1e-5f);
    }
}

// ------------- normalize (+relu | +residual) with dual destination ---------
__global__ void norm_apply(const float* __restrict__ x, const float* __restrict__ res,
                           float* __restrict__ o1, float* __restrict__ o2,
                           const float* __restrict__ mean, const float* __restrict__ rstd,
                           int C, int HW, int c1tot, int c1base,
                           int c2tot, int c2base, int relu, int N)
{
    int i = blockIdx.x * 256 + threadIdx.x;
    if (i >= N) return;
    int hw = i % HW;
    int bc = i / HW;
    int c  = bc % C;
    int b  = bc / C;
    float v = (x[i] - mean[bc]) * rstd[bc];
    if (relu) v = fmaxf(v, 0.f);
    if (res)  v += res[i];
    o1[((size_t)(b * c1tot + c1base + c)) * HW + hw] = v;
    if (o2) o2[((size_t)(b * c2tot + c2base + c)) * HW + hw] = v;
}

// ------------------- channel-slice copy (build concat buffers) -------------
__global__ void copy_ch(const float* __restrict__ src, float* __restrict__ dst,
                        int C, int HW, int ctot, int cbase, int N)
{
    int i = blockIdx.x * 256 + threadIdx.x;
    if (i >= N) return;
    int hw = i % HW;
    int bc = i / HW;
    int c  = bc % C;
    int b  = bc / C;
    dst[((size_t)(b * ctot + cbase + c)) * HW + hw] = src[i];
}

// --------------- deformable-conv column builder (bilinear+mask) ------------
// om is stored as nSlices partial buffers (stride floats apart) to be summed.
__global__ void dcn_col(const float* __restrict__ img, const float* __restrict__ om,
                        float* __restrict__ col, int C, int H, int W,
                        int nSlices, size_t stride)
{
    int p = blockIdx.x * 256 + threadIdx.x;
    int k = blockIdx.y;
    int b = blockIdx.z;
    int HW = H * W;
    if (p >= HW) return;
    int y = p / W, x = p % W;

    size_t base = (size_t)b * 27 * HW;
    float dy = 0.f, dx = 0.f, mr = 0.f;
    for (int s = 0; s < nSlices; s++) {
        const float* omS = om + s * stride + base;
        dy += omS[(2 * k    ) * HW + p];
        dx += omS[(2 * k + 1) * HW + p];
        mr += omS[(18 + k) * HW + p];
    }
    float mv = 1.f / (1.f + expf(-mr));

    float py = (float)(y + k / 3 - 1) + dy;
    float px = (float)(x + k % 3 - 1) + dx;
    float fy = floorf(py), fx = floorf(px);
    int y0 = (int)fy, x0 = (int)fx;
    float wy1 = py - fy, wx1 = px - fx;
    float wy0 = 1.f - wy1, wx0 = 1.f - wx1;

    bool vy0 = (y0 >= 0)     && (y0 < H);
    bool vy1 = (y0 + 1 >= 0) && (y0 + 1 < H);
    bool vx0 = (x0 >= 0)     && (x0 < W);
    bool vx1 = (x0 + 1 >= 0) && (x0 + 1 < W);

    float w00 = (vy0 && vx0) ? wy0 * wx0 * mv : 0.f;
    float w01 = (vy0 && vx1) ? wy0 * wx1 * mv : 0.f;
    float w10 = (vy1 && vx0) ? wy1 * wx0 * mv : 0.f;
    float w11 = (vy1 && vx1) ? wy1 * wx1 * mv : 0.f;

    int cy0 = min(max(y0, 0), H - 1);
    int cy1 = min(max(y0 + 1, 0), H - 1);
    int cx0 = min(max(x0, 0), W - 1);
    int cx1 = min(max(x0 + 1, 0), W - 1);
    int i00 = cy0 * W + cx0, i01 = cy0 * W + cx1;
    int i10 = cy1 * W + cx0, i11 = cy1 * W + cx1;

    const float* ib = img + (size_t)b * C * HW;
    float* cb = col + ((size_t)b * C * 9 + k) * HW + p;
    for (int ci = 0; ci < C; ci++) {
        const float* ic = ib + (size_t)ci * HW;
        float v = w00 * ic[i00] + w01 * ic[i01] + w10 * ic[i10] + w11 * ic[i11];
        cb[(size_t)ci * 9 * HW] = v;
    }
}

// ------------------------ |offset| mean reductions --------------------------
__global__ void absmean_partial(const float* __restrict__ om,
                                float* __restrict__ part, int HW,
                                int nSlices, size_t stride)
{
    long N = 144L * HW;  // 8 batches * 18 channels
    float s = 0.f;
    long gs = 64L * 256;
    for (long i = (long)blockIdx.x * 256 + threadIdx.x; i < N; i += gs) {
        int hw = (int)(i % HW);
        int t  = (int)(i / HW);
        int c = t % 18, b = t / 18;
        size_t idx = ((size_t)b * 27 + c) * HW + hw;
        float v = 0.f;
        for (int sl = 0; sl < nSlices; sl++) v += om[sl * stride + idx];
        s += fabsf(v);
    }
#pragma unroll
    for (int o = 16; o; o >>= 1) s += __shfl_down_sync(0xffffffffu, s, o);
    __shared__ float sh[8];
    if ((threadIdx.x & 31) == 0) sh[threadIdx.x >> 5] = s;
    __syncthreads();
    if (threadIdx.x == 0) {
        float t2 = 0.f;
        for (int i = 0; i < 8; i++) t2 += sh[i];
        part[blockIdx.x] = t2;
    }
}

__global__ void finalize_offset(const float* __restrict__ pA, const float* __restrict__ pB,
                                float* __restrict__ dst, float invA, float invB)
{
    float sA = 0.f, sB = 0.f;
    for (int i = 0; i < 64; i++) { sA += pA[i]; sB += pB[i]; }
    dst[0] = 0.5f * (sA * invA + sB * invB);
}

// -------------------------------- host side --------------------------------
static inline dim3 cgrid(int H, int W, int Cout, int zMul = 1)
{
    return dim3((unsigned)((W / 32) * (H / 16)),
                (unsigned)((Cout + 15) / 16), BATCH * zMul);
}

extern "C" void kernel_launch(void* const* d_in, const int* in_sizes, int n_in,
                              void* d_out, int out_size)
{
    (void)in_sizes; (void)n_in; (void)out_size;
    const float* x        = (const float*)d_in[0];
    const float* skip1    = (const float*)d_in[1];
    const float* skip2    = (const float*)d_in[2];
    const float* rb_w1[2] = {(const float*)d_in[3], (const float*)d_in[7]};
    const float* rb_b1[2] = {(const float*)d_in[4], (const float*)d_in[8]};
    const float* rb_w2[2] = {(const float*)d_in[5], (const float*)d_in[9]};
    const float* rb_b2[2] = {(const float*)d_in[6], (const float*)d_in[10]};
    const float* conv1_w = (const float*)d_in[11]; const float* conv1_b = (const float*)d_in[12];
    const float* conv3_w = (const float*)d_in[13]; const float* conv3_b = (const float*)d_in[14];
    const float* conv5_w = (const float*)d_in[15]; const float* conv5_b = (const float*)d_in[16];
    const float* conv6_w = (const float*)d_in[17]; const float* conv6_b = (const float*)d_in[18];
    const float* dcn2_ow = (const float*)d_in[19]; const float* dcn2_ob = (const float*)d_in[20];
    const float* dcn2_w  = (const float*)d_in[21]; const float* dcn2_b  = (const float*)d_in[22];
    const float* dcn1_ow = (const float*)d_in[23]; const float* dcn1_ob = (const float*)d_in[24];
    const float* dcn1_w  = (const float*)d_in[25]; const float* dcn1_b  = (const float*)d_in[26];
    float* out = (float*)d_out;

    float* arena = nullptr;
    cudaGetSymbolAddress((void**)&arena, g_arena);
    float* A    = arena + OFF_A;
    float* Bf   = arena + OFF_B;
    float* Cf   = arena + OFF_C;
    float* dc2  = arena + OFF_DC2;
    float* out3 = arena + OFF_OUT3;
    float* om2  = arena + OFF_OM2;
    float* col2 = arena + OFF_COL2;
    float* t64  = arena + OFF_T64;
    float* dc1  = arena + OFF_DC1;
    float* out5 = arena + OFF_OUT5;
    float* om1  = arena + OFF_OM1;
    float* col1 = arena + OFF_COL1;
    float* t128 = arena + OFF_T128;
    float* gm   = arena + OFF_MEAN;
    float* gr   = arena + OFF_RSTD;
    float* pA   = arena + OFF_PA;
    float* pB   = arena + OFF_PB;

    auto c3r = conv_kernel<3, 4, 16, 2, true,  false>;
    auto c3z = conv_kernel<3, 4, 16, 2, false, false>;
    auto c5r = conv_kernel<5, 2, 16, 2, true,  false>;
    auto c5u = conv_kernel<5, 2, 16, 2, true,  true >;
    auto c7r = conv_kernel<7, 2, 16, 2, true,  false>;
    auto c1k = conv_kernel<1, 16, 16, 2, false, false>;

    const int N32_256 = 8 * 256 * 1024;
    const int N64_128 = 8 * 128 * 4096;
    const int N128_64 = 8 * 64 * 16384;

    const size_t OM2_SL = (size_t)8 * 27 * 1024;
    const size_t OM1_SL = (size_t)8 * 27 * 4096;

    // ---- ResBlock 0 ----
    c3r<<<cgrid(32, 32, 256), 256>>>(x,  rb_w1[0], rb_b1[0], A, 256, 256, 32, 32, 1, 256, 0, 0, 256, 1, 0);
    stats_kernel<<<8 * 256, 256>>>(A, gm, gr, 1024);
    norm_apply<<<(N32_256 + 255) / 256, 256>>>(A, nullptr, Bf, nullptr, gm, gr, 256, 1024, 256, 0, 0, 0, 1, N32_256);
    c3r<<<cgrid(32, 32, 256), 256>>>(Bf, rb_w2[0], rb_b2[0], A, 256, 256, 32, 32, 1, 256, 0, 0, 256, 1, 0);
    stats_kernel<<<8 * 256, 256>>>(A, gm, gr, 1024);
    norm_apply<<<(N32_256 + 255) / 256, 256>>>(A, x, Cf, nullptr, gm, gr, 256, 1024, 256, 0, 0, 0, 0, N32_256);

    // ---- ResBlock 1 ----
    c3r<<<cgrid(32, 32, 256), 256>>>(Cf, rb_w1[1], rb_b1[1], A, 256, 256, 32, 32, 1, 256, 0, 0, 256, 1, 0);
    stats_kernel<<<8 * 256, 256>>>(A, gm, gr, 1024);
    norm_apply<<<(N32_256 + 255) / 256, 256>>>(A, nullptr, Bf, nullptr, gm, gr, 256, 1024, 256, 0, 0, 0, 1, N32_256);
    c3r<<<cgrid(32, 32, 256), 256>>>(Bf, rb_w2[1], rb_b2[1], A, 256, 256, 32, 32, 1, 256, 0, 0, 256, 1, 0);
    stats_kernel<<<8 * 256, 256>>>(A, gm, gr, 1024);
    norm_apply<<<(N32_256 + 255) / 256, 256>>>(A, Cf, Bf, nullptr, gm, gr, 256, 1024, 256, 0, 0, 0, 0, N32_256);
    // out1 in Bf

    // ---- Conv2dBlock 5x5 256->256 ----
    c5r<<<cgrid(32, 32, 256), 256>>>(Bf, conv1_w, conv1_b, A, 256, 256, 32, 32, 2, 256, 0, 0, 256, 1, 0);
    stats_kernel<<<8 * 256, 256>>>(A, gm, gr, 1024);
    norm_apply<<<(N32_256 + 255) / 256, 256>>>(A, nullptr, dc2, out3, gm, gr, 256, 1024, 512, 0, 512, 256, 1, N32_256);
    copy_ch<<<(N32_256 + 255) / 256, 256>>>(skip2, dc2, 256, 1024, 512, 256, N32_256);

    // ---- DCN2 (offset conv split 4-way over Cin=512) ----
    c3z<<<cgrid(32, 32, 27, 4), 256>>>(dc2, dcn2_ow, dcn2_ob, om2, 512, 27, 32, 32, 1, 27, 0, 0, 128, 4, OM2_SL);
    dcn_col<<<dim3(4, 9, BATCH), 256>>>(skip2, om2, col2, 256, 32, 32, 4, OM2_SL);
    c1k<<<cgrid(32, 32, 256), 256>>>(col2, dcn2_w, dcn2_b, out3, 2304, 256, 32, 32, 0, 512, 0, 0, 2304, 1, 0);
    absmean_partial<<<64, 256>>>(om2, pA, 1024, 4, OM2_SL);

    // ---- upsample(x2) fused + Conv2dBlock 5x5 512->128 ----
    c5u<<<cgrid(64, 64, 128), 256>>>(out3, conv3_w, conv3_b, t64, 512, 128, 64, 64, 2, 128, 0, 0, 512, 1, 0);
    stats_kernel<<<8 * 128, 256>>>(t64, gm, gr, 4096);
    norm_apply<<<(N64_128 + 255) / 256, 256>>>(t64, nullptr, dc1, out5, gm, gr, 128, 4096, 256, 0, 256, 128, 1, N64_128);
    copy_ch<<<(N64_128 + 255) / 256, 256>>>(skip1, dc1, 128, 4096, 256, 128, N64_128);

    // ---- DCN1 (offset conv split 2-way over Cin=256) ----
    c3z<<<cgrid(64, 64, 27, 2), 256>>>(dc1, dcn1_ow, dcn1_ob, om1, 256, 27, 64, 64, 1, 27, 0, 0, 128, 2, OM1_SL);
    dcn_col<<<dim3(16, 9, BATCH), 256>>>(skip1, om1, col1, 128, 64, 64, 2, OM1_SL);
    c1k<<<cgrid(64, 64, 128), 256>>>(col1, dcn1_w, dcn1_b, out5, 1152, 128, 64, 64, 0, 256, 0, 0, 1152, 1, 0);
    absmean_partial<<<64, 256>>>(om1, pB, 4096, 2, OM1_SL);

    // ---- upsample(x2) fused + Conv2dBlock 5x5 256->64 ----
    c5u<<<cgrid(128, 128, 64), 256>>>(out5, conv5_w, conv5_b, t128, 256, 64, 128, 128, 2, 64, 0, 0, 256, 1, 0);
    stats_kernel<<<8 * 64, 256>>>(t128, gm, gr, 16384);
    norm_apply<<<(N128_64 + 255) / 256, 256>>>(t128, nullptr, t128, nullptr, gm, gr, 64, 16384, 64, 0, 0, 0, 1, N128_64);

    // ---- final 7x7 64->3 + tanh, straight to d_out ----
    c7r<<<cgrid(128, 128, 3), 256>>>(t128, conv6_w, conv6_b, out, 64, 3, 128, 128, 3, 3, 0, 1, 64, 1, 0);

    // ---- offset_sum scalar at end of d_out ----
    finalize_offset<<<1, 1>>>(pA, pB, out + 8 * 3 * 128 * 128,
                              1.f / 147456.f, 1.f / 589824.f);
}